// round 15
// baseline (speedup 1.0000x reference)
#include <cuda_runtime.h>

typedef unsigned long long u64;

#define B_   32
#define C_   3
#define T_   4096
#define V_   25
#define P_   1024
#define O_   128
#define K_   24      // 3 channels * 8 patch samples
#define F_   28
#define PT   16      // patches per block
#define NT   (4*PT + 4)   // 68 time samples per block
#define PPAD 18      // p-dim pad (72B row stride, 8B aligned, STS conflict-free)
#define TPB  256

#define XW_BYTES (K_ * V_ * PPAD * 4)        // 43200
#define GD_BYTES (K_ * 16 * 10 * 8)          // 30720
#define SMEM_BYTES (XW_BYTES + GD_BYTES)     // 73920  -> 3 CTAs/SM

__device__ float2 g_Gd[K_ * O_];   // duplicated pairs, [k][o] = (g,g)

// ---------------------------------------------------------------------------
// Setup: build sM (28x8, 2-level symmetric DWT of an 8-sample patch) in
// parallel, fuse with W into duplicated pairs. 1 block, 256 threads.
// ---------------------------------------------------------------------------
__global__ void build_G(const float* __restrict__ W) {
    __shared__ float sA1[7][8], sD1[7][8];
    __shared__ float sM[F_][8];
    const int tid = threadIdx.x;

    const float DEC_LO[8] = {
        -0.010597401784997278f,  0.032883011666982945f,
         0.030841381835986965f, -0.18703481171888114f,
        -0.02798376941698385f,   0.6308807679295904f,
         0.7148465705525415f,    0.23037781330885523f };
    const float DEC_HI[8] = {
        -0.23037781330885523f,   0.7148465705525415f,
        -0.6308807679295904f,   -0.02798376941698385f,
         0.18703481171888114f,   0.030841381835986965f,
        -0.032883011666982945f, -0.010597401784997278f };

    if (tid < 56) {
        int i = tid >> 3, k = tid & 7;
        float a = 0.f, d = 0.f;
        for (int j = 0; j < 8; j++) {
            int s = 2 * i + j - 6;
            if (s < 0)  s = -1 - s;
            if (s >= 8) s = 15 - s;
            if (s == k) { a += DEC_LO[7 - j]; d += DEC_HI[7 - j]; }
        }
        sA1[i][k] = a; sD1[i][k] = d;
    }
    __syncthreads();

    if (tid < 56) {
        int i = tid >> 3, k = tid & 7;
        float aa = 0.f, ad = 0.f, da = 0.f, dd = 0.f;
        for (int j = 0; j < 8; j++) {
            int s = 2 * i + j - 6;
            if (s < 0)  s = -1 - s;
            if (s >= 7) s = 13 - s;
            float lo = DEC_LO[7 - j], hi = DEC_HI[7 - j];
            aa += lo * sA1[s][k];  ad += hi * sA1[s][k];
            da += lo * sD1[s][k];  dd += hi * sD1[s][k];
        }
        // Feature order in reference: [aa, ad, dd, da]
        sM[i][k]      = aa;
        sM[7 + i][k]  = ad;
        sM[14 + i][k] = dd;
        sM[21 + i][k] = da;
    }
    __syncthreads();

    if (tid < O_) {
        int o = tid;
        for (int c = 0; c < C_; c++)
            for (int k = 0; k < 8; k++) {
                float g = 0.f;
                for (int f = 0; f < F_; f++)
                    g += W[o * (C_ * F_) + c * F_ + f] * sM[f][k];
                g_Gd[(c * 8 + k) * O_ + o] = make_float2(g, g);
            }
    }
}

// ---------------------------------------------------------------------------
// Fused kernel.  Block = (16-patch tile, batch): 400 positions x 128 channels.
// Warp = 4 pos-subgroups (4 pos each, one v) x 8 ch-groups of 8 ch.
// Thread tile 4 pos x 8 ch -> acc[2][8] (32 regs).
// Per k per warp: 2 LDS.64 (x, 4 addrs, CF) + 4 LDS.128 (G, 8 addrs @80B
// stride, banks 20c mod 32 distinct, CF) + 16 fma.rn.f32x2  => 6 wavefronts.
// ---------------------------------------------------------------------------
__global__ void __launch_bounds__(TPB, 3)
wavelet_fused(const float* __restrict__ x, float* __restrict__ out) {
    extern __shared__ __align__(16) char smem[];
    float (*xw)[V_][PPAD] = reinterpret_cast<float (*)[V_][PPAD]>(smem);
    u64   (*gd)[16][10]   = reinterpret_cast<u64   (*)[16][10]>(smem + XW_BYTES);

    const int b   = blockIdx.y;
    const int pt0 = blockIdx.x * PT;
    const int t0  = 4 * pt0;
    const int tid = threadIdx.x;

    // --- stage dup-G: gd[k][grp of 8 ch][8 pairs + 2 pad] ---
    for (int idx = tid; idx < K_ * O_; idx += TPB) {
        int k = idx >> 7;
        int o = idx & (O_ - 1);
        const float2 d = g_Gd[idx];
        gd[k][o >> 3][o & 7] = *reinterpret_cast<const u64*>(&d);
    }

    // --- stage x: coalesced read, windowed scatter ---
    const float* xb = x + (size_t)b * C_ * T_ * V_;
    for (int idx = tid; idx < C_ * NT * V_; idx += TPB) {
        int c  = idx / (NT * V_);
        int r  = idx - c * (NT * V_);
        int tl = r / V_;
        int v  = r - tl * V_;
        int t  = t0 + tl;
        if (t > T_ - 1) t = T_ - 1;          // edge padding
        float val = xb[(c * T_ + t) * V_ + v];
        int p = tl >> 2, j = tl & 3;
        if (p < PT)   xw[c * 8 + j][v][p]         = val;
        if (p >= 1)   xw[c * 8 + j + 4][v][p - 1] = val;
    }
    __syncthreads();

    // --- GEMM: 25 v x 2 ch-halves = 50 warp-tiles over 8 warps ---
    const int warp = tid >> 5, lane = tid & 31;
    const int sub  = lane >> 3;         // pos-subgroup 0..3 (4 pos each)
    const int cg   = lane & 7;          // ch-group within half (8 ch each)

#pragma unroll 1
    for (int wt = warp; wt < 50; wt += 8) {
        const int v     = wt >> 1;
        const int chalf = wt & 1;                // fixed per warp (step 8)
        const int pl0   = sub * 4;
        const int grp   = chalf * 8 + cg;        // 8-ch group, 0..15
        const int ch0   = grp * 8;

        u64 acc[2][8];
#pragma unroll
        for (int pp = 0; pp < 2; pp++)
#pragma unroll
            for (int c = 0; c < 8; c++) acc[pp][c] = 0ULL;

#pragma unroll 2
        for (int k = 0; k < K_; k++) {
            const u64* xk = reinterpret_cast<const u64*>(&xw[k][v][pl0]);
            u64 xv[2];
            xv[0] = xk[0];                       // LDS.64, 4 addrs, CF
            xv[1] = xk[1];

            const ulonglong2* gk = reinterpret_cast<const ulonglong2*>(&gd[k][grp][0]);
            u64 gv[8];
#pragma unroll
            for (int q = 0; q < 4; q++) {        // LDS.128 x4, 8 addrs, CF
                ulonglong2 gg = gk[q];
                gv[2 * q]     = gg.x;
                gv[2 * q + 1] = gg.y;
            }

#pragma unroll
            for (int pp = 0; pp < 2; pp++)
#pragma unroll
                for (int c = 0; c < 8; c++)
                    asm("fma.rn.f32x2 %0, %1, %2, %0;"
                        : "+l"(acc[pp][c]) : "l"(gv[c]), "l"(xv[pp]));
        }

        float* obase = out + (((size_t)(b * V_ + v) * P_ + pt0 + pl0) << 7) + ch0;
#pragma unroll
        for (int pp = 0; pp < 2; pp++) {
            float lo[8], hi[8];
#pragma unroll
            for (int c = 0; c < 8; c++)
                asm("mov.b64 {%0, %1}, %2;" : "=f"(lo[c]), "=f"(hi[c]) : "l"(acc[pp][c]));
            float* r0 = obase + (size_t)(2 * pp) * O_;
            *reinterpret_cast<float4*>(r0)          = make_float4(lo[0], lo[1], lo[2], lo[3]);
            *reinterpret_cast<float4*>(r0 + 4)      = make_float4(lo[4], lo[5], lo[6], lo[7]);
            *reinterpret_cast<float4*>(r0 + O_)     = make_float4(hi[0], hi[1], hi[2], hi[3]);
            *reinterpret_cast<float4*>(r0 + O_ + 4) = make_float4(hi[4], hi[5], hi[6], hi[7]);
        }
    }
}

// ---------------------------------------------------------------------------
extern "C" void kernel_launch(void* const* d_in, const int* in_sizes, int n_in,
                              void* d_out, int out_size) {
    const float* x = (const float*)d_in[0];
    const float* W = (const float*)d_in[1];
    if (n_in >= 2 && in_sizes[0] < in_sizes[1]) {
        const float* t = x; x = W; W = t;
    }

    static int attr_set = 0;
    if (!attr_set) {
        cudaFuncSetAttribute(wavelet_fused,
                             cudaFuncAttributeMaxDynamicSharedMemorySize, SMEM_BYTES);
        attr_set = 1;
    }

    build_G<<<1, 256>>>(W);

    dim3 grid(P_ / PT, B_);
    wavelet_fused<<<grid, TPB, SMEM_BYTES>>>(x, (float*)d_out);
}